// round 2
// baseline (speedup 1.0000x reference)
#include <cuda_runtime.h>
#include <cstdint>

#define FULLMASK 0xffffffffu

// ---------------- scratch (device globals; no allocations in kernel_launch) ----
__device__ float g_gates[2048 * 1024];   // pre-activation gates
__device__ float g_ww[2048 * 1024];      // write-attn logits -> softmax weights
__device__ float g_hnew[2048 * 256];     // LSTM hidden output
__device__ float g_erase[2048 * 32];     // erase vectors
__device__ float g_add[2048 * 32];       // add vectors
__device__ float g_gate_bias[1024];      // b_ih + b_hh + W_ih[:,256:] @ rd
__device__ float g_out_bias[256];        // b_out + W_out[:,256:] @ rd

__device__ __forceinline__ float sigmf(float x) { return 1.f / (1.f + __expf(-x)); }

// ---------------- k0: setup — softmax(b_rattn), rd, folded biases -------------
__global__ __launch_bounds__(256) void setup_kernel(
    const float* __restrict__ b_rattn, const float* __restrict__ memory,
    const float* __restrict__ W_ih, const float* __restrict__ b_ih,
    const float* __restrict__ b_hh, const float* __restrict__ W_out,
    const float* __restrict__ b_out)
{
    __shared__ float wr[1024];
    __shared__ float red[32];
    __shared__ float bc;
    __shared__ float part[8 * 32];
    __shared__ float rd_s[32];
    const int t = threadIdx.x;
    const int lane = t & 31, w = t >> 5;

    // softmax over b_rattn (h=0 => logits == b_rattn, shared by all batch rows)
    float mx = -1e30f;
    for (int i = t; i < 1024; i += 256) { float v = b_rattn[i]; wr[i] = v; mx = fmaxf(mx, v); }
#pragma unroll
    for (int o = 16; o; o >>= 1) mx = fmaxf(mx, __shfl_xor_sync(FULLMASK, mx, o));
    if (lane == 0) red[w] = mx;
    __syncthreads();
    if (t == 0) { float m = red[0]; for (int i = 1; i < 8; i++) m = fmaxf(m, red[i]); bc = m; }
    __syncthreads();
    mx = bc;
    float s = 0.f;
    for (int i = t; i < 1024; i += 256) { float e = __expf(wr[i] - mx); wr[i] = e; s += e; }
#pragma unroll
    for (int o = 16; o; o >>= 1) s += __shfl_xor_sync(FULLMASK, s, o);
    __syncthreads();
    if (lane == 0) red[w] = s;
    __syncthreads();
    if (t == 0) { float ss = 0.f; for (int i = 0; i < 8; i++) ss += red[i]; bc = ss; }
    __syncthreads();
    const float inv = 1.f / bc;
    for (int i = t; i < 1024; i += 256) wr[i] *= inv;
    __syncthreads();

    // rd[d] = sum_m wr[m] * memory[m, d]
    {
        const int d = lane, pp = w;       // 8 partitions x 128 rows
        float acc = 0.f;
        const int m0 = pp * 128;
        for (int m = m0; m < m0 + 128; m++) acc += wr[m] * memory[m * 32 + d];
        part[pp * 32 + d] = acc;
    }
    __syncthreads();
    if (t < 32) { float r = 0.f; for (int p = 0; p < 8; p++) r += part[p * 32 + t]; rd_s[t] = r; }
    __syncthreads();

    // gate_bias[j] = b_ih[j] + b_hh[j] + W_ih[j, 256:288] . rd
    for (int j = t; j < 1024; j += 256) {
        float g = b_ih[j] + b_hh[j];
        const float* wp = W_ih + (size_t)j * 288 + 256;
#pragma unroll
        for (int d = 0; d < 32; d++) g += wp[d] * rd_s[d];
        g_gate_bias[j] = g;
    }
    // out_bias[o] = b_out[o] + W_out[o, 256:288] . rd
    {
        float g = b_out[t];
        const float* wp = W_out + (size_t)t * 288 + 256;
#pragma unroll
        for (int d = 0; d < 32; d++) g += wp[d] * rd_s[d];
        g_out_bias[t] = g;
    }
}

// ---------------- SGEMM: out[M=2048, N=1024] = A[2048,256] @ W[N, ldw].T + bias
// 128x128 tile, BK=8, 256 threads, 8x8 per thread.
// MODE 0: A = x (param), bias = g_gate_bias, out = g_gates
// MODE 1: A = g_hnew,   bias = b_wattn (param), out = g_ww
template <int MODE>
__global__ __launch_bounds__(256) void sgemm_k256(
    const float* __restrict__ Aext, const float* __restrict__ W, int ldw,
    const float* __restrict__ biasext)
{
    __shared__ float As[8][128];
    __shared__ float Bs[8][128];
    const int n0 = blockIdx.x * 128, m0 = blockIdx.y * 128;
    const int tid = threadIdx.x;
    const int trow = tid >> 4, tcol = tid & 15;
    const int arow = tid >> 1, ac = (tid & 1) * 4;

    const float* A = (MODE == 0) ? Aext : g_hnew;
    const float* bias = (MODE == 0) ? g_gate_bias : biasext;
    float* outp = (MODE == 0) ? g_gates : g_ww;

    const float* Ap = A + (size_t)(m0 + arow) * 256 + ac;
    const float* Wp = W + (size_t)(n0 + arow) * ldw + ac;

    float acc[8][8];
#pragma unroll
    for (int i = 0; i < 8; i++)
#pragma unroll
        for (int j = 0; j < 8; j++) acc[i][j] = 0.f;

    for (int k0 = 0; k0 < 256; k0 += 8) {
        const float4 av = *(const float4*)(Ap + k0);
        const float4 bv = *(const float4*)(Wp + k0);
        As[ac + 0][arow] = av.x; As[ac + 1][arow] = av.y;
        As[ac + 2][arow] = av.z; As[ac + 3][arow] = av.w;
        Bs[ac + 0][arow] = bv.x; Bs[ac + 1][arow] = bv.y;
        Bs[ac + 2][arow] = bv.z; Bs[ac + 3][arow] = bv.w;
        __syncthreads();
#pragma unroll
        for (int k = 0; k < 8; k++) {
            const float4 a0 = *(const float4*)&As[k][trow * 8];
            const float4 a1 = *(const float4*)&As[k][trow * 8 + 4];
            const float4 b0 = *(const float4*)&Bs[k][tcol * 8];
            const float4 b1 = *(const float4*)&Bs[k][tcol * 8 + 4];
            const float ra[8] = {a0.x, a0.y, a0.z, a0.w, a1.x, a1.y, a1.z, a1.w};
            const float rb[8] = {b0.x, b0.y, b0.z, b0.w, b1.x, b1.y, b1.z, b1.w};
#pragma unroll
            for (int i = 0; i < 8; i++)
#pragma unroll
                for (int j = 0; j < 8; j++) acc[i][j] += ra[i] * rb[j];
        }
        __syncthreads();
    }
#pragma unroll
    for (int i = 0; i < 8; i++) {
        const int m = m0 + trow * 8 + i;
        float* orow = outp + (size_t)m * 1024 + n0 + tcol * 8;
#pragma unroll
        for (int j = 0; j < 8; j++) orow[j] = acc[i][j] + bias[n0 + tcol * 8 + j];
    }
}

// ---------------- k2: LSTM activations (c=0 => c_new = sig(i)*tanh(g)) -------
__global__ __launch_bounds__(256) void activ_kernel()
{
    const int idx = blockIdx.x * 256 + threadIdx.x;  // 2048*256
    const int b = idx >> 8, cc = idx & 255;
    const float* g = g_gates + (size_t)b * 1024;
    const float ig = g[cc], gg = g[512 + cc], og = g[768 + cc];
    const float cnew = sigmf(ig) * tanhf(gg);
    g_hnew[idx] = sigmf(og) * tanhf(cnew);
}

// ---------------- k4: row softmax over g_ww [2048 x 1024], in place ----------
__global__ __launch_bounds__(256) void softmax1024()
{
    __shared__ float red[32];
    __shared__ float bc;
    float* p = g_ww + (size_t)blockIdx.x * 1024;
    const int t = threadIdx.x, lane = t & 31, w = t >> 5;
    float v[4];
    float mx = -1e30f;
#pragma unroll
    for (int i = 0; i < 4; i++) { v[i] = p[t + i * 256]; mx = fmaxf(mx, v[i]); }
#pragma unroll
    for (int o = 16; o; o >>= 1) mx = fmaxf(mx, __shfl_xor_sync(FULLMASK, mx, o));
    if (lane == 0) red[w] = mx;
    __syncthreads();
    if (t == 0) { float m = red[0]; for (int i = 1; i < 8; i++) m = fmaxf(m, red[i]); bc = m; }
    __syncthreads();
    mx = bc;
    float s = 0.f;
#pragma unroll
    for (int i = 0; i < 4; i++) { v[i] = __expf(v[i] - mx); s += v[i]; }
#pragma unroll
    for (int o = 16; o; o >>= 1) s += __shfl_xor_sync(FULLMASK, s, o);
    __syncthreads();
    if (lane == 0) red[w] = s;
    __syncthreads();
    if (t == 0) { float ss = 0.f; for (int i = 0; i < 8; i++) ss += red[i]; bc = ss; }
    __syncthreads();
    const float inv = 1.f / bc;
#pragma unroll
    for (int i = 0; i < 4; i++) p[t + i * 256] = v[i] * inv;
}

// ---------------- k5: fused head GEMM (erase | add | output), N=320, K=256 ---
__global__ __launch_bounds__(256) void head_gemm(
    const float* __restrict__ W_er, const float* __restrict__ b_er,
    const float* __restrict__ W_ad, const float* __restrict__ b_ad,
    const float* __restrict__ W_out, float* __restrict__ out_main)
{
    __shared__ float As[8][128];
    __shared__ float Bs[8][128];
    const int n0 = blockIdx.x * 128, m0 = blockIdx.y * 128;
    const int tid = threadIdx.x;
    const int trow = tid >> 4, tcol = tid & 15;
    const int arow = tid >> 1, ac = (tid & 1) * 4;

    const float* Ap = g_hnew + (size_t)(m0 + arow) * 256 + ac;
    const int n = n0 + arow;
    const float* Wp;
    bool valid = true;
    if (n < 32)       Wp = W_er + (size_t)n * 256;
    else if (n < 64)  Wp = W_ad + (size_t)(n - 32) * 256;
    else if (n < 320) Wp = W_out + (size_t)(n - 64) * 288;
    else { Wp = W_er; valid = false; }
    Wp += ac;

    float acc[8][8];
#pragma unroll
    for (int i = 0; i < 8; i++)
#pragma unroll
        for (int j = 0; j < 8; j++) acc[i][j] = 0.f;

    for (int k0 = 0; k0 < 256; k0 += 8) {
        const float4 av = *(const float4*)(Ap + k0);
        float4 bv = make_float4(0.f, 0.f, 0.f, 0.f);
        if (valid) bv = *(const float4*)(Wp + k0);
        As[ac + 0][arow] = av.x; As[ac + 1][arow] = av.y;
        As[ac + 2][arow] = av.z; As[ac + 3][arow] = av.w;
        Bs[ac + 0][arow] = bv.x; Bs[ac + 1][arow] = bv.y;
        Bs[ac + 2][arow] = bv.z; Bs[ac + 3][arow] = bv.w;
        __syncthreads();
#pragma unroll
        for (int k = 0; k < 8; k++) {
            const float4 a0 = *(const float4*)&As[k][trow * 8];
            const float4 a1 = *(const float4*)&As[k][trow * 8 + 4];
            const float4 b0 = *(const float4*)&Bs[k][tcol * 8];
            const float4 b1 = *(const float4*)&Bs[k][tcol * 8 + 4];
            const float ra[8] = {a0.x, a0.y, a0.z, a0.w, a1.x, a1.y, a1.z, a1.w};
            const float rb[8] = {b0.x, b0.y, b0.z, b0.w, b1.x, b1.y, b1.z, b1.w};
#pragma unroll
            for (int i = 0; i < 8; i++)
#pragma unroll
                for (int j = 0; j < 8; j++) acc[i][j] += ra[i] * rb[j];
        }
        __syncthreads();
    }
#pragma unroll
    for (int i = 0; i < 8; i++) {
        const int m = m0 + trow * 8 + i;
#pragma unroll
        for (int j = 0; j < 8; j++) {
            const int nn = n0 + tcol * 8 + j;
            const float vv = acc[i][j];
            if (nn < 32)        g_erase[m * 32 + nn] = sigmf(vv + b_er[nn]);
            else if (nn < 64)   g_add[m * 32 + nn - 32] = tanhf(vv + b_ad[nn - 32]);
            else if (nn < 320)  out_main[(size_t)m * 256 + nn - 64] = vv + g_out_bias[nn - 64];
        }
    }
}

// ---------------- k6: write_data (268 MB streaming stores) -------------------
__global__ __launch_bounds__(256) void write_mem(
    const float* __restrict__ memory, float* __restrict__ outw)
{
    const int b = blockIdx.y;
    const int t = threadIdx.x;
    const int d4 = (t & 7) * 4;
    const int mbase = blockIdx.x * 256 + (t >> 3);
    const float4 ev = *(const float4*)(g_erase + b * 32 + d4);
    const float4 av = *(const float4*)(g_add + b * 32 + d4);
    const float* wwb = g_ww + (size_t)b * 1024;
    float* ob = outw + (size_t)b * 32768;
#pragma unroll
    for (int it = 0; it < 8; it++) {
        const int m = mbase + it * 32;
        const float wv = wwb[m];
        const float4 mv = *(const float4*)(memory + m * 32 + d4);
        float4 r;
        // mem*(1 - w*e) + w*a  ==  mem - w*(mem*e - a)
        r.x = mv.x - wv * (mv.x * ev.x - av.x);
        r.y = mv.y - wv * (mv.y * ev.y - av.y);
        r.z = mv.z - wv * (mv.z * ev.z - av.z);
        r.w = mv.w - wv * (mv.w * ev.w - av.w);
        __stcs((float4*)(ob + (size_t)m * 32 + d4), r);
    }
}

// ---------------- launch -----------------------------------------------------
extern "C" void kernel_launch(void* const* d_in, const int* in_sizes, int n_in,
                              void* d_out, int out_size)
{
    const float* x       = (const float*)d_in[0];
    const float* memory  = (const float*)d_in[1];
    const float* b_rattn = (const float*)d_in[3];
    const float* W_ih    = (const float*)d_in[4];
    const float* b_ih    = (const float*)d_in[6];
    const float* b_hh    = (const float*)d_in[7];
    const float* W_wattn = (const float*)d_in[8];
    const float* b_wattn = (const float*)d_in[9];
    const float* W_er    = (const float*)d_in[10];
    const float* b_er    = (const float*)d_in[11];
    const float* W_ad    = (const float*)d_in[12];
    const float* b_ad    = (const float*)d_in[13];
    const float* W_out   = (const float*)d_in[14];
    const float* b_out   = (const float*)d_in[15];
    float* out = (float*)d_out;

    setup_kernel<<<1, 256>>>(b_rattn, memory, W_ih, b_ih, b_hh, W_out, b_out);
    sgemm_k256<0><<<dim3(8, 16), 256>>>(x, W_ih, 288, nullptr);
    activ_kernel<<<2048, 256>>>();
    sgemm_k256<1><<<dim3(8, 16), 256>>>(nullptr, W_wattn, 256, b_wattn);
    softmax1024<<<2048, 256>>>();
    head_gemm<<<dim3(3, 16), 256>>>(W_er, b_er, W_ad, b_ad, W_out, out);
    write_mem<<<dim3(4, 2048), 256>>>(memory, out + 2048 * 256);
}

// round 3
// speedup vs baseline: 1.0692x; 1.0692x over previous
#include <cuda_runtime.h>
#include <cstdint>

#define FULLMASK 0xffffffffu

// ---------------- scratch (device globals; no allocations) -------------------
__device__ float g_gates[2048 * 768];    // pre-activation gates (i|g|o), f dropped
__device__ float g_ww[2048 * 1024];      // write-attn logits
__device__ float g_hnew[2048 * 256];     // LSTM hidden output
__device__ float g_erase[2048 * 32];     // erase vectors
__device__ float g_add[2048 * 32];       // add vectors
__device__ float g_gate_bias[1024];      // b_ih + b_hh + W_ih[:,256:] @ rd  (original 1024 idx)
__device__ float g_out_bias[256];        // b_out + W_out[:,256:] @ rd

__device__ __forceinline__ float sigmf(float x) { return 1.f / (1.f + __expf(-x)); }

// ---------------- k0: setup — softmax(b_rattn), rd, folded biases -------------
__global__ __launch_bounds__(256) void setup_kernel(
    const float* __restrict__ b_rattn, const float* __restrict__ memory,
    const float* __restrict__ W_ih, const float* __restrict__ b_ih,
    const float* __restrict__ b_hh, const float* __restrict__ W_out,
    const float* __restrict__ b_out)
{
    __shared__ float wr[1024];
    __shared__ float red[32];
    __shared__ float bc;
    __shared__ float part[8 * 32];
    __shared__ float rd_s[32];
    const int t = threadIdx.x;
    const int lane = t & 31, w = t >> 5;

    float mx = -1e30f;
    for (int i = t; i < 1024; i += 256) { float v = b_rattn[i]; wr[i] = v; mx = fmaxf(mx, v); }
#pragma unroll
    for (int o = 16; o; o >>= 1) mx = fmaxf(mx, __shfl_xor_sync(FULLMASK, mx, o));
    if (lane == 0) red[w] = mx;
    __syncthreads();
    if (t == 0) { float m = red[0]; for (int i = 1; i < 8; i++) m = fmaxf(m, red[i]); bc = m; }
    __syncthreads();
    mx = bc;
    float s = 0.f;
    for (int i = t; i < 1024; i += 256) { float e = __expf(wr[i] - mx); wr[i] = e; s += e; }
#pragma unroll
    for (int o = 16; o; o >>= 1) s += __shfl_xor_sync(FULLMASK, s, o);
    __syncthreads();
    if (lane == 0) red[w] = s;
    __syncthreads();
    if (t == 0) { float ss = 0.f; for (int i = 0; i < 8; i++) ss += red[i]; bc = ss; }
    __syncthreads();
    const float inv = 1.f / bc;
    for (int i = t; i < 1024; i += 256) wr[i] *= inv;
    __syncthreads();

    {
        const int d = lane, pp = w;
        float acc = 0.f;
        const int m0 = pp * 128;
        for (int m = m0; m < m0 + 128; m++) acc += wr[m] * memory[m * 32 + d];
        part[pp * 32 + d] = acc;
    }
    __syncthreads();
    if (t < 32) { float r = 0.f; for (int p = 0; p < 8; p++) r += part[p * 32 + t]; rd_s[t] = r; }
    __syncthreads();

    for (int j = t; j < 1024; j += 256) {
        float g = b_ih[j] + b_hh[j];
        const float* wp = W_ih + (size_t)j * 288 + 256;
#pragma unroll
        for (int d = 0; d < 32; d++) g += wp[d] * rd_s[d];
        g_gate_bias[j] = g;
    }
    {
        float g = b_out[t];
        const float* wp = W_out + (size_t)t * 288 + 256;
#pragma unroll
        for (int d = 0; d < 32; d++) g += wp[d] * rd_s[d];
        g_out_bias[t] = g;
    }
}

// ---------------- double-buffered SGEMM: 64(M) x 128(N) x 16(K) tiles --------
// 256 threads, thread tile 4x8. A[M,256] row-major. W rows mapped per MODE.
// MODE 0: A=x, N=768, W=W_ih (ldw 288, row remap n+(n>=256?256:0)), out g_gates+gate_bias
// MODE 1: A=g_hnew, N=1024, W=W_wattn (ldw 256), out g_ww + b_wattn
// MODE 2: A=g_hnew, N=384(pad of 320), W rows: [0,32)=W_er, [32,64)=W_ad, [64,320)=W_out
//         epilogue scatters into g_erase/g_add/out_main with activations.
template <int MODE>
__global__ __launch_bounds__(256) void gemm_db(
    const float* __restrict__ Aext, const float* __restrict__ W,
    const float* __restrict__ bias,
    const float* __restrict__ W_er, const float* __restrict__ b_er,
    const float* __restrict__ W_ad, const float* __restrict__ b_ad,
    float* __restrict__ out_main)
{
    __shared__ float As[2][16][64];
    __shared__ float Bs[2][16][128];

    const int tid = threadIdx.x;
    const int m0 = blockIdx.y * 64, n0 = blockIdx.x * 128;
    const int arow = tid >> 2;            // 0..63
    const int acol = (tid & 3) * 4;       // 0,4,8,12
    const int tm = tid >> 4, tn = tid & 15;

    const float* A = (MODE == 0) ? Aext : g_hnew;
    const float* Ap = A + (size_t)(m0 + arow) * 256 + acol;

    const int r1 = n0 + arow, r2 = r1 + 64;
    const float *Wp1, *Wp2;
    bool v1 = true, v2 = true;
    if (MODE == 0) {
        Wp1 = W + (size_t)(r1 + (r1 >= 256 ? 256 : 0)) * 288;
        Wp2 = W + (size_t)(r2 + (r2 >= 256 ? 256 : 0)) * 288;
    } else if (MODE == 1) {
        Wp1 = W + (size_t)r1 * 256;
        Wp2 = W + (size_t)r2 * 256;
    } else {
        if (r1 < 32)       Wp1 = W_er + (size_t)r1 * 256;
        else if (r1 < 64)  Wp1 = W_ad + (size_t)(r1 - 32) * 256;
        else if (r1 < 320) Wp1 = W + (size_t)(r1 - 64) * 288;
        else { Wp1 = W_er; v1 = false; }
        if (r2 < 32)       Wp2 = W_er + (size_t)r2 * 256;
        else if (r2 < 64)  Wp2 = W_ad + (size_t)(r2 - 32) * 256;
        else if (r2 < 320) Wp2 = W + (size_t)(r2 - 64) * 288;
        else { Wp2 = W_er; v2 = false; }
    }
    Wp1 += acol; Wp2 += acol;

    float acc[4][8];
#pragma unroll
    for (int i = 0; i < 4; i++)
#pragma unroll
        for (int j = 0; j < 8; j++) acc[i][j] = 0.f;

    const float4 z4 = make_float4(0.f, 0.f, 0.f, 0.f);
    float4 pa, pb0, pb1;

    // chunk 0
    pa = *(const float4*)(Ap);
    pb0 = v1 ? *(const float4*)(Wp1) : z4;
    pb1 = v2 ? *(const float4*)(Wp2) : z4;
    As[0][acol + 0][arow] = pa.x;  As[0][acol + 1][arow] = pa.y;
    As[0][acol + 2][arow] = pa.z;  As[0][acol + 3][arow] = pa.w;
    Bs[0][acol + 0][arow] = pb0.x; Bs[0][acol + 1][arow] = pb0.y;
    Bs[0][acol + 2][arow] = pb0.z; Bs[0][acol + 3][arow] = pb0.w;
    Bs[0][acol + 0][arow + 64] = pb1.x; Bs[0][acol + 1][arow + 64] = pb1.y;
    Bs[0][acol + 2][arow + 64] = pb1.z; Bs[0][acol + 3][arow + 64] = pb1.w;
    __syncthreads();

    int buf = 0;
#pragma unroll 1
    for (int c = 1; c < 16; c++) {
        const int k0 = c * 16;
        pa = *(const float4*)(Ap + k0);
        pb0 = v1 ? *(const float4*)(Wp1 + k0) : z4;
        pb1 = v2 ? *(const float4*)(Wp2 + k0) : z4;
#pragma unroll
        for (int k = 0; k < 16; k++) {
            const float4 a = *(const float4*)&As[buf][k][tm * 4];
            const float4 b0 = *(const float4*)&Bs[buf][k][tn * 8];
            const float4 b1 = *(const float4*)&Bs[buf][k][tn * 8 + 4];
            const float ra[4] = {a.x, a.y, a.z, a.w};
            const float rb[8] = {b0.x, b0.y, b0.z, b0.w, b1.x, b1.y, b1.z, b1.w};
#pragma unroll
            for (int i = 0; i < 4; i++)
#pragma unroll
                for (int j = 0; j < 8; j++) acc[i][j] += ra[i] * rb[j];
        }
        const int nb = buf ^ 1;
        As[nb][acol + 0][arow] = pa.x;  As[nb][acol + 1][arow] = pa.y;
        As[nb][acol + 2][arow] = pa.z;  As[nb][acol + 3][arow] = pa.w;
        Bs[nb][acol + 0][arow] = pb0.x; Bs[nb][acol + 1][arow] = pb0.y;
        Bs[nb][acol + 2][arow] = pb0.z; Bs[nb][acol + 3][arow] = pb0.w;
        Bs[nb][acol + 0][arow + 64] = pb1.x; Bs[nb][acol + 1][arow + 64] = pb1.y;
        Bs[nb][acol + 2][arow + 64] = pb1.z; Bs[nb][acol + 3][arow + 64] = pb1.w;
        __syncthreads();
        buf = nb;
    }
#pragma unroll
    for (int k = 0; k < 16; k++) {
        const float4 a = *(const float4*)&As[buf][k][tm * 4];
        const float4 b0 = *(const float4*)&Bs[buf][k][tn * 8];
        const float4 b1 = *(const float4*)&Bs[buf][k][tn * 8 + 4];
        const float ra[4] = {a.x, a.y, a.z, a.w};
        const float rb[8] = {b0.x, b0.y, b0.z, b0.w, b1.x, b1.y, b1.z, b1.w};
#pragma unroll
        for (int i = 0; i < 4; i++)
#pragma unroll
            for (int j = 0; j < 8; j++) acc[i][j] += ra[i] * rb[j];
    }

    // ----- epilogues -----
    if (MODE == 0) {
        float bj[8];
#pragma unroll
        for (int j = 0; j < 8; j++) {
            const int n = n0 + tn * 8 + j;
            bj[j] = g_gate_bias[n + (n >= 256 ? 256 : 0)];
        }
#pragma unroll
        for (int i = 0; i < 4; i++) {
            const int m = m0 + tm * 4 + i;
            float* orow = g_gates + (size_t)m * 768 + n0 + tn * 8;
#pragma unroll
            for (int j = 0; j < 8; j++) orow[j] = acc[i][j] + bj[j];
        }
    } else if (MODE == 1) {
        float bj[8];
#pragma unroll
        for (int j = 0; j < 8; j++) bj[j] = bias[n0 + tn * 8 + j];
#pragma unroll
        for (int i = 0; i < 4; i++) {
            const int m = m0 + tm * 4 + i;
            float* orow = g_ww + (size_t)m * 1024 + n0 + tn * 8;
#pragma unroll
            for (int j = 0; j < 8; j++) orow[j] = acc[i][j] + bj[j];
        }
    } else {
#pragma unroll
        for (int i = 0; i < 4; i++) {
            const int m = m0 + tm * 4 + i;
#pragma unroll
            for (int j = 0; j < 8; j++) {
                const int n = n0 + tn * 8 + j;
                const float vv = acc[i][j];
                if (n < 32)        g_erase[m * 32 + n] = sigmf(vv + b_er[n]);
                else if (n < 64)   g_add[m * 32 + n - 32] = tanhf(vv + b_ad[n - 32]);
                else if (n < 320)  out_main[(size_t)m * 256 + n - 64] = vv + g_out_bias[n - 64];
            }
        }
    }
}

// ---------------- k2: LSTM activations over compact (i|g|o) layout -----------
__global__ __launch_bounds__(256) void activ_kernel()
{
    const int idx = blockIdx.x * 256 + threadIdx.x;  // 2048*256
    const int b = idx >> 8, cc = idx & 255;
    const float* g = g_gates + (size_t)b * 768;
    const float ig = g[cc], gg = g[256 + cc], og = g[512 + cc];
    const float cnew = sigmf(ig) * tanhf(gg);
    g_hnew[idx] = sigmf(og) * tanhf(cnew);
}

// ---------------- k5: fused row-softmax + memory write (268 MB streaming) ----
__global__ __launch_bounds__(256) void softmax_write(
    const float* __restrict__ memory, float* __restrict__ outw)
{
    __shared__ float wsm[1024];
    __shared__ float red[8];
    __shared__ float bc;
    const int b = blockIdx.x;
    const int t = threadIdx.x, lane = t & 31, w = t >> 5;
    const float* p = g_ww + (size_t)b * 1024;

    float v[4];
    float mx = -1e30f;
#pragma unroll
    for (int i = 0; i < 4; i++) { v[i] = p[t + i * 256]; mx = fmaxf(mx, v[i]); }
#pragma unroll
    for (int o = 16; o; o >>= 1) mx = fmaxf(mx, __shfl_xor_sync(FULLMASK, mx, o));
    if (lane == 0) red[w] = mx;
    __syncthreads();
    if (t == 0) { float m = red[0]; for (int i = 1; i < 8; i++) m = fmaxf(m, red[i]); bc = m; }
    __syncthreads();
    mx = bc;
    float s = 0.f;
#pragma unroll
    for (int i = 0; i < 4; i++) { v[i] = __expf(v[i] - mx); s += v[i]; }
#pragma unroll
    for (int o = 16; o; o >>= 1) s += __shfl_xor_sync(FULLMASK, s, o);
    __syncthreads();
    if (lane == 0) red[w] = s;
    __syncthreads();
    if (t == 0) { float ss = 0.f; for (int i = 0; i < 8; i++) ss += red[i]; bc = ss; }
    __syncthreads();
    const float inv = 1.f / bc;
#pragma unroll
    for (int i = 0; i < 4; i++) wsm[t + i * 256] = v[i] * inv;
    __syncthreads();

    // stream write_data for this batch row
    const int d4 = (t & 7) * 4;
    const int mbase = t >> 3;               // 0..31
    const float4 ev = *(const float4*)(g_erase + b * 32 + d4);
    const float4 av = *(const float4*)(g_add + b * 32 + d4);
    float* ob = outw + (size_t)b * 32768;
#pragma unroll 4
    for (int it = 0; it < 32; it++) {
        const int m = mbase + it * 32;
        const float wv = wsm[m];
        const float4 mv = *(const float4*)(memory + m * 32 + d4);
        float4 r;
        r.x = mv.x - wv * (mv.x * ev.x - av.x);
        r.y = mv.y - wv * (mv.y * ev.y - av.y);
        r.z = mv.z - wv * (mv.z * ev.z - av.z);
        r.w = mv.w - wv * (mv.w * ev.w - av.w);
        __stcs((float4*)(ob + (size_t)m * 32 + d4), r);
    }
}

// ---------------- launch -----------------------------------------------------
extern "C" void kernel_launch(void* const* d_in, const int* in_sizes, int n_in,
                              void* d_out, int out_size)
{
    const float* x       = (const float*)d_in[0];
    const float* memory  = (const float*)d_in[1];
    const float* b_rattn = (const float*)d_in[3];
    const float* W_ih    = (const float*)d_in[4];
    const float* b_ih    = (const float*)d_in[6];
    const float* b_hh    = (const float*)d_in[7];
    const float* W_wattn = (const float*)d_in[8];
    const float* b_wattn = (const float*)d_in[9];
    const float* W_er    = (const float*)d_in[10];
    const float* b_er    = (const float*)d_in[11];
    const float* W_ad    = (const float*)d_in[12];
    const float* b_ad    = (const float*)d_in[13];
    const float* W_out   = (const float*)d_in[14];
    const float* b_out   = (const float*)d_in[15];
    float* out = (float*)d_out;

    setup_kernel<<<1, 256>>>(b_rattn, memory, W_ih, b_ih, b_hh, W_out, b_out);
    gemm_db<0><<<dim3(6, 32), 256>>>(x, W_ih, nullptr,
                                     nullptr, nullptr, nullptr, nullptr, nullptr);
    activ_kernel<<<2048, 256>>>();
    gemm_db<1><<<dim3(8, 32), 256>>>(nullptr, W_wattn, b_wattn,
                                     nullptr, nullptr, nullptr, nullptr, nullptr);
    gemm_db<2><<<dim3(3, 32), 256>>>(nullptr, W_out, nullptr,
                                     W_er, b_er, W_ad, b_ad, out);
    softmax_write<<<2048, 256>>>(memory, out + 2048 * 256);
}

// round 4
// speedup vs baseline: 1.5267x; 1.4279x over previous
#include <cuda_runtime.h>
#include <cuda_bf16.h>
#include <cstdint>

#define FULLMASK 0xffffffffu

// ---------------- scratch (device globals; no allocations) -------------------
__device__ float g_gates[2048 * 768];          // pre-activation gates (i|g|o)
__device__ float g_ww[2048 * 1024];            // write-attn logits
__device__ float g_erase[2048 * 32];
__device__ float g_add[2048 * 32];
__device__ float g_gate_bias[1024];            // indexed by ORIGINAL 1024 gate idx
__device__ float g_out_bias[256];

// bf16 split buffers (K expanded 256 -> 768: [hi | lo | hi] for A, [hi | hi | lo] for B)
__device__ __nv_bfloat16 g_xs[2048 * 768];     // split of x
__device__ __nv_bfloat16 g_hs[2048 * 768];     // split of h_new
__device__ __nv_bfloat16 g_Bih[768 * 768];     // split W_ih (i|g|o rows)
__device__ __nv_bfloat16 g_Bww[1024 * 768];    // split W_wattn
__device__ __nv_bfloat16 g_Bhead[384 * 768];   // split [W_er|W_ad|W_out|zeros]

__device__ __forceinline__ float sigmf(float x) { return 1.f / (1.f + __expf(-x)); }

// ---------------- mma / ldmatrix helpers -------------------------------------
__device__ __forceinline__ void ldsm4(uint32_t& r0, uint32_t& r1, uint32_t& r2,
                                      uint32_t& r3, uint32_t addr)
{
    asm volatile("ldmatrix.sync.aligned.m8n8.x4.shared.b16 {%0,%1,%2,%3}, [%4];"
                 : "=r"(r0), "=r"(r1), "=r"(r2), "=r"(r3) : "r"(addr));
}
__device__ __forceinline__ void mma16816(float& d0, float& d1, float& d2, float& d3,
                                         uint32_t a0, uint32_t a1, uint32_t a2, uint32_t a3,
                                         uint32_t b0, uint32_t b1)
{
    asm volatile(
        "mma.sync.aligned.m16n8k16.row.col.f32.bf16.bf16.f32 "
        "{%0,%1,%2,%3}, {%4,%5,%6,%7}, {%8,%9}, {%0,%1,%2,%3};"
        : "+f"(d0), "+f"(d1), "+f"(d2), "+f"(d3)
        : "r"(a0), "r"(a1), "r"(a2), "r"(a3), "r"(b0), "r"(b1));
}

// ---------------- k0: setup — softmax(b_rattn), rd, folded biases -------------
__global__ __launch_bounds__(256) void setup_kernel(
    const float* __restrict__ b_rattn, const float* __restrict__ memory,
    const float* __restrict__ W_ih, const float* __restrict__ b_ih,
    const float* __restrict__ b_hh, const float* __restrict__ W_out,
    const float* __restrict__ b_out)
{
    __shared__ float wr[1024];
    __shared__ float red[32];
    __shared__ float bc;
    __shared__ float part[8 * 32];
    __shared__ float rd_s[32];
    const int t = threadIdx.x;
    const int lane = t & 31, w = t >> 5;

    float mx = -1e30f;
    for (int i = t; i < 1024; i += 256) { float v = b_rattn[i]; wr[i] = v; mx = fmaxf(mx, v); }
#pragma unroll
    for (int o = 16; o; o >>= 1) mx = fmaxf(mx, __shfl_xor_sync(FULLMASK, mx, o));
    if (lane == 0) red[w] = mx;
    __syncthreads();
    if (t == 0) { float m = red[0]; for (int i = 1; i < 8; i++) m = fmaxf(m, red[i]); bc = m; }
    __syncthreads();
    mx = bc;
    float s = 0.f;
    for (int i = t; i < 1024; i += 256) { float e = __expf(wr[i] - mx); wr[i] = e; s += e; }
#pragma unroll
    for (int o = 16; o; o >>= 1) s += __shfl_xor_sync(FULLMASK, s, o);
    __syncthreads();
    if (lane == 0) red[w] = s;
    __syncthreads();
    if (t == 0) { float ss = 0.f; for (int i = 0; i < 8; i++) ss += red[i]; bc = ss; }
    __syncthreads();
    const float inv = 1.f / bc;
    for (int i = t; i < 1024; i += 256) wr[i] *= inv;
    __syncthreads();

    {
        const int d = lane, pp = w;
        float acc = 0.f;
        const int m0 = pp * 128;
        for (int m = m0; m < m0 + 128; m++) acc += wr[m] * memory[m * 32 + d];
        part[pp * 32 + d] = acc;
    }
    __syncthreads();
    if (t < 32) { float r = 0.f; for (int p = 0; p < 8; p++) r += part[p * 32 + t]; rd_s[t] = r; }
    __syncthreads();

    for (int j = t; j < 1024; j += 256) {
        float g = b_ih[j] + b_hh[j];
        const float* wp = W_ih + (size_t)j * 288 + 256;
#pragma unroll
        for (int d = 0; d < 32; d++) g += wp[d] * rd_s[d];
        g_gate_bias[j] = g;
    }
    {
        float g = b_out[t];
        const float* wp = W_out + (size_t)t * 288 + 256;
#pragma unroll
        for (int d = 0; d < 32; d++) g += wp[d] * rd_s[d];
        g_out_bias[t] = g;
    }
}

// ---------------- split helpers ----------------------------------------------
__device__ __forceinline__ void split_write_A(__nv_bfloat16* dst, int stride_row_base,
                                              float v)
{
    // dst points at [row*768 + k]; writes hi @k, lo @k+256, hi @k+512
    __nv_bfloat16 hi = __float2bfloat16_rn(v);
    float r = v - __bfloat162float(hi);
    __nv_bfloat16 lo = __float2bfloat16_rn(r);
    dst[0] = hi; dst[256] = lo; dst[512] = hi;
    (void)stride_row_base;
}
__device__ __forceinline__ void split_write_B(__nv_bfloat16* dst, float v)
{
    // B layout: hi @k, hi @k+256, lo @k+512
    __nv_bfloat16 hi = __float2bfloat16_rn(v);
    float r = v - __bfloat162float(hi);
    __nv_bfloat16 lo = __float2bfloat16_rn(r);
    dst[0] = hi; dst[256] = hi; dst[512] = lo;
}

// ---------------- k1: convert x -> g_xs --------------------------------------
__global__ __launch_bounds__(256) void conv_x_kernel(const float* __restrict__ x)
{
    const int b = blockIdx.x, k = threadIdx.x;
    split_write_A(g_xs + (size_t)b * 768 + k, 0, x[b * 256 + k]);
}

// ---------------- k2: convert all weights -> g_Bih / g_Bww / g_Bhead ---------
__global__ __launch_bounds__(256) void conv_w_kernel(
    const float* __restrict__ W_ih, const float* __restrict__ W_wattn,
    const float* __restrict__ W_er, const float* __restrict__ W_ad,
    const float* __restrict__ W_out)
{
    const int r = blockIdx.x, k = threadIdx.x;
    float v; __nv_bfloat16* dst;
    if (r < 768) {                               // gates i|g|o
        const int orig = r + (r >= 256 ? 256 : 0);
        v = W_ih[(size_t)orig * 288 + k];
        dst = g_Bih + (size_t)r * 768 + k;
    } else if (r < 1792) {                       // W_wattn
        const int rw = r - 768;
        v = W_wattn[(size_t)rw * 256 + k];
        dst = g_Bww + (size_t)rw * 768 + k;
    } else {                                     // head
        const int rh = r - 1792;
        if (rh < 32)       v = W_er[(size_t)rh * 256 + k];
        else if (rh < 64)  v = W_ad[(size_t)(rh - 32) * 256 + k];
        else if (rh < 320) v = W_out[(size_t)(rh - 64) * 288 + k];
        else               v = 0.f;
        dst = g_Bhead + (size_t)rh * 768 + k;
    }
    split_write_B(dst, v);
}

// ---------------- bf16 MMA GEMM: 128x128 tile, K'=768, double buffered -------
// MODE 0: A=g_xs,  B=g_Bih  (N=768),  out g_gates + gate_bias(remap)
// MODE 1: A=g_hs,  B=g_Bww  (N=1024), out g_ww + b_wattn
// MODE 2: A=g_hs,  B=g_Bhead(N=384),  scatter erase/add/output
template <int MODE>
__global__ __launch_bounds__(256, 2) void mma_gemm(
    const float* __restrict__ bias, const float* __restrict__ b_er,
    const float* __restrict__ b_ad, float* __restrict__ out_main)
{
    __shared__ __nv_bfloat16 As[2][128][40];
    __shared__ __nv_bfloat16 Bs[2][128][40];

    const int tid = threadIdx.x;
    const int wid = tid >> 5, lane = tid & 31;
    const int m0 = blockIdx.y * 128, n0 = blockIdx.x * 128;
    const int warp_m = wid >> 2, warp_n = wid & 3;   // 2 x 4 warps

    const __nv_bfloat16* A = (MODE == 0) ? g_xs : g_hs;
    const __nv_bfloat16* B = (MODE == 0) ? g_Bih : (MODE == 1) ? g_Bww : g_Bhead;

    // loader: thread t handles row t>>1, 16 cols starting at (t&1)*16
    const int lrow = tid >> 1;
    const int lcol = (tid & 1) * 16;
    const __nv_bfloat16* Ag = A + (size_t)(m0 + lrow) * 768 + lcol;
    const __nv_bfloat16* Bg = B + (size_t)(n0 + lrow) * 768 + lcol;

    float acc[4][4][4];
#pragma unroll
    for (int i = 0; i < 4; i++)
#pragma unroll
        for (int j = 0; j < 4; j++)
#pragma unroll
            for (int q = 0; q < 4; q++) acc[i][j][q] = 0.f;

    // prologue: chunk 0
    int4 ra0 = *(const int4*)(Ag);
    int4 ra1 = *(const int4*)(Ag + 8);
    int4 rb0 = *(const int4*)(Bg);
    int4 rb1 = *(const int4*)(Bg + 8);
    *(int4*)&As[0][lrow][lcol] = ra0;  *(int4*)&As[0][lrow][lcol + 8] = ra1;
    *(int4*)&Bs[0][lrow][lcol] = rb0;  *(int4*)&Bs[0][lrow][lcol + 8] = rb1;
    __syncthreads();

    const int NC = 24;   // 768 / 32
#pragma unroll 1
    for (int c = 0; c < NC; c++) {
        if (c + 1 < NC) {
            const int off = (c + 1) * 32;
            ra0 = *(const int4*)(Ag + off);
            ra1 = *(const int4*)(Ag + off + 8);
            rb0 = *(const int4*)(Bg + off);
            rb1 = *(const int4*)(Bg + off + 8);
        }
        const int buf = c & 1;
        const uint32_t abase = (uint32_t)__cvta_generic_to_shared(&As[buf][0][0]);
        const uint32_t bbase = (uint32_t)__cvta_generic_to_shared(&Bs[buf][0][0]);
#pragma unroll
        for (int kk = 0; kk < 2; kk++) {
            const int k16 = kk * 16;
            uint32_t af[4][4];
#pragma unroll
            for (int mi = 0; mi < 4; mi++) {
                const int rr = warp_m * 64 + mi * 16 + (lane & 15);
                const int cc = k16 + ((lane >> 4) << 3);
                ldsm4(af[mi][0], af[mi][1], af[mi][2], af[mi][3],
                      abase + (uint32_t)(rr * 40 + cc) * 2);
            }
            uint32_t bf[2][4];
#pragma unroll
            for (int bi = 0; bi < 2; bi++) {
                const int rr = warp_n * 32 + bi * 16 + ((lane >> 4) << 3) + (lane & 7);
                const int cc = k16 + (((lane >> 3) & 1) << 3);
                ldsm4(bf[bi][0], bf[bi][1], bf[bi][2], bf[bi][3],
                      bbase + (uint32_t)(rr * 40 + cc) * 2);
            }
#pragma unroll
            for (int mi = 0; mi < 4; mi++)
#pragma unroll
                for (int nj = 0; nj < 4; nj++) {
                    const uint32_t b0 = bf[nj >> 1][(nj & 1) * 2];
                    const uint32_t b1 = bf[nj >> 1][(nj & 1) * 2 + 1];
                    mma16816(acc[mi][nj][0], acc[mi][nj][1], acc[mi][nj][2], acc[mi][nj][3],
                             af[mi][0], af[mi][1], af[mi][2], af[mi][3], b0, b1);
                }
        }
        if (c + 1 < NC) {
            const int nb = (c + 1) & 1;
            *(int4*)&As[nb][lrow][lcol] = ra0;  *(int4*)&As[nb][lrow][lcol + 8] = ra1;
            *(int4*)&Bs[nb][lrow][lcol] = rb0;  *(int4*)&Bs[nb][lrow][lcol + 8] = rb1;
            __syncthreads();
        }
    }

    // ----- epilogue -----
    const int erow = (lane >> 2);
    const int ecol = (lane & 3) * 2;
#pragma unroll
    for (int mi = 0; mi < 4; mi++) {
        const int r0 = m0 + warp_m * 64 + mi * 16 + erow;
#pragma unroll
        for (int nj = 0; nj < 4; nj++) {
            const int cbase = n0 + warp_n * 32 + nj * 8 + ecol;
            const float v0 = acc[mi][nj][0], v1 = acc[mi][nj][1];
            const float v2 = acc[mi][nj][2], v3 = acc[mi][nj][3];
            if (MODE == 0) {
                const float bz0 = g_gate_bias[cbase + (cbase >= 256 ? 256 : 0)];
                const float bz1 = g_gate_bias[cbase + 1 + (cbase + 1 >= 256 ? 256 : 0)];
                float* p0 = g_gates + (size_t)r0 * 768 + cbase;
                p0[0] = v0 + bz0; p0[1] = v1 + bz1;
                float* p1 = p0 + 8 * 768;
                p1[0] = v2 + bz0; p1[1] = v3 + bz1;
            } else if (MODE == 1) {
                const float bz0 = bias[cbase], bz1 = bias[cbase + 1];
                float* p0 = g_ww + (size_t)r0 * 1024 + cbase;
                p0[0] = v0 + bz0; p0[1] = v1 + bz1;
                float* p1 = p0 + 8 * 1024;
                p1[0] = v2 + bz0; p1[1] = v3 + bz1;
            } else {
#pragma unroll
                for (int q = 0; q < 4; q++) {
                    const int m = r0 + (q >= 2 ? 8 : 0);
                    const int n = cbase + (q & 1);
                    const float vv = (q == 0) ? v0 : (q == 1) ? v1 : (q == 2) ? v2 : v3;
                    if (n < 32)        g_erase[m * 32 + n] = sigmf(vv + b_er[n]);
                    else if (n < 64)   g_add[m * 32 + n - 32] = tanhf(vv + b_ad[n - 32]);
                    else if (n < 320)  out_main[(size_t)m * 256 + n - 64] = vv + g_out_bias[n - 64];
                }
            }
        }
    }
}

// ---------------- k4: LSTM activations -> h_new -> bf16 split g_hs -----------
__global__ __launch_bounds__(256) void activ_kernel()
{
    const int idx = blockIdx.x * 256 + threadIdx.x;  // 2048*256
    const int b = idx >> 8, cc = idx & 255;
    const float* g = g_gates + (size_t)b * 768;
    const float ig = g[cc], gg = g[256 + cc], og = g[512 + cc];
    const float cnew = sigmf(ig) * tanhf(gg);
    const float h = sigmf(og) * tanhf(cnew);
    split_write_A(g_hs + (size_t)b * 768 + cc, 0, h);
}

// ---------------- k7: fused row-softmax + memory write (268 MB) --------------
__global__ __launch_bounds__(256) void softmax_write(
    const float* __restrict__ memory, float* __restrict__ outw)
{
    __shared__ float wsm[1024];
    __shared__ float red[8];
    __shared__ float bc;
    const int b = blockIdx.x;
    const int t = threadIdx.x, lane = t & 31, w = t >> 5;
    const float* p = g_ww + (size_t)b * 1024;

    float v[4];
    float mx = -1e30f;
#pragma unroll
    for (int i = 0; i < 4; i++) { v[i] = p[t + i * 256]; mx = fmaxf(mx, v[i]); }
#pragma unroll
    for (int o = 16; o; o >>= 1) mx = fmaxf(mx, __shfl_xor_sync(FULLMASK, mx, o));
    if (lane == 0) red[w] = mx;
    __syncthreads();
    if (t == 0) { float m = red[0]; for (int i = 1; i < 8; i++) m = fmaxf(m, red[i]); bc = m; }
    __syncthreads();
    mx = bc;
    float s = 0.f;
#pragma unroll
    for (int i = 0; i < 4; i++) { v[i] = __expf(v[i] - mx); s += v[i]; }
#pragma unroll
    for (int o = 16; o; o >>= 1) s += __shfl_xor_sync(FULLMASK, s, o);
    __syncthreads();
    if (lane == 0) red[w] = s;
    __syncthreads();
    if (t == 0) { float ss = 0.f; for (int i = 0; i < 8; i++) ss += red[i]; bc = ss; }
    __syncthreads();
    const float inv = 1.f / bc;
#pragma unroll
    for (int i = 0; i < 4; i++) wsm[t + i * 256] = v[i] * inv;
    __syncthreads();

    const int d4 = (t & 7) * 4;
    const int mbase = t >> 3;
    const float4 ev = *(const float4*)(g_erase + b * 32 + d4);
    const float4 av = *(const float4*)(g_add + b * 32 + d4);
    float* ob = outw + (size_t)b * 32768;
#pragma unroll 4
    for (int it = 0; it < 32; it++) {
        const int m = mbase + it * 32;
        const float wv = wsm[m];
        const float4 mv = *(const float4*)(memory + m * 32 + d4);
        float4 r;
        r.x = mv.x - wv * (mv.x * ev.x - av.x);
        r.y = mv.y - wv * (mv.y * ev.y - av.y);
        r.z = mv.z - wv * (mv.z * ev.z - av.z);
        r.w = mv.w - wv * (mv.w * ev.w - av.w);
        __stcs((float4*)(ob + (size_t)m * 32 + d4), r);
    }
}

// ---------------- launch -----------------------------------------------------
extern "C" void kernel_launch(void* const* d_in, const int* in_sizes, int n_in,
                              void* d_out, int out_size)
{
    const float* x       = (const float*)d_in[0];
    const float* memory  = (const float*)d_in[1];
    const float* b_rattn = (const float*)d_in[3];
    const float* W_ih    = (const float*)d_in[4];
    const float* b_ih    = (const float*)d_in[6];
    const float* b_hh    = (const float*)d_in[7];
    const float* W_wattn = (const float*)d_in[8];
    const float* b_wattn = (const float*)d_in[9];
    const float* W_er    = (const float*)d_in[10];
    const float* b_er    = (const float*)d_in[11];
    const float* W_ad    = (const float*)d_in[12];
    const float* b_ad    = (const float*)d_in[13];
    const float* W_out   = (const float*)d_in[14];
    const float* b_out   = (const float*)d_in[15];
    float* out = (float*)d_out;

    conv_x_kernel<<<2048, 256>>>(x);
    conv_w_kernel<<<2176, 256>>>(W_ih, W_wattn, W_er, W_ad, W_out);
    setup_kernel<<<1, 256>>>(b_rattn, memory, W_ih, b_ih, b_hh, W_out, b_out);
    mma_gemm<0><<<dim3(6, 16), 256>>>(nullptr, nullptr, nullptr, nullptr);
    activ_kernel<<<2048, 256>>>();
    mma_gemm<1><<<dim3(8, 16), 256>>>(b_wattn, nullptr, nullptr, nullptr);
    mma_gemm<2><<<dim3(3, 16), 256>>>(nullptr, b_er, b_ad, out);
    softmax_write<<<2048, 256>>>(memory, out + 2048 * 256);
}

// round 5
// speedup vs baseline: 1.7971x; 1.1771x over previous
#include <cuda_runtime.h>
#include <cuda_bf16.h>
#include <cstdint>

#define FULLMASK 0xffffffffu

// ---------------- scratch (device globals; no allocations) -------------------
__device__ float g_gates[2048 * 768];          // pre-activation gates (i|g|o)
__device__ float g_ww[2048 * 1024];            // write-attn logits -> weights
__device__ float g_erase[2048 * 32];
__device__ float g_add[2048 * 32];
__device__ float g_gate_bias[1024];            // indexed by ORIGINAL 1024 gate idx
__device__ float g_out_bias[256];

// bf16 split buffers (K expanded 256 -> 768: A=[hi|lo|hi], B=[hi|hi|lo])
__device__ __nv_bfloat16 g_xs[2048 * 768];
__device__ __nv_bfloat16 g_hs[2048 * 768];
__device__ __nv_bfloat16 g_Bih[768 * 768];     // W_ih gate rows (i|g|o)
__device__ __nv_bfloat16 g_Bcomb[1408 * 768];  // [W_wattn(1024) | W_er|W_ad|W_out|pad (384)]

__device__ __forceinline__ float sigmf(float x) { return 1.f / (1.f + __expf(-x)); }

// ---------------- PTX helpers -------------------------------------------------
__device__ __forceinline__ void ldsm4(uint32_t& r0, uint32_t& r1, uint32_t& r2,
                                      uint32_t& r3, uint32_t addr)
{
    asm volatile("ldmatrix.sync.aligned.m8n8.x4.shared.b16 {%0,%1,%2,%3}, [%4];"
                 : "=r"(r0), "=r"(r1), "=r"(r2), "=r"(r3) : "r"(addr));
}
__device__ __forceinline__ void mma16816(float& d0, float& d1, float& d2, float& d3,
                                         uint32_t a0, uint32_t a1, uint32_t a2, uint32_t a3,
                                         uint32_t b0, uint32_t b1)
{
    asm volatile(
        "mma.sync.aligned.m16n8k16.row.col.f32.bf16.bf16.f32 "
        "{%0,%1,%2,%3}, {%4,%5,%6,%7}, {%8,%9}, {%0,%1,%2,%3};"
        : "+f"(d0), "+f"(d1), "+f"(d2), "+f"(d3)
        : "r"(a0), "r"(a1), "r"(a2), "r"(a3), "r"(b0), "r"(b1));
}
__device__ __forceinline__ void cpasync16(uint32_t dst, const void* src)
{
    asm volatile("cp.async.cg.shared.global [%0], [%1], 16;" :: "r"(dst), "l"(src));
}
__device__ __forceinline__ void cpcommit() { asm volatile("cp.async.commit_group;"); }
__device__ __forceinline__ void cpwait1() { asm volatile("cp.async.wait_group 1;"); }

// ---------------- k0: setup — softmax(b_rattn), rd, folded biases -------------
__global__ __launch_bounds__(256) void setup_kernel(
    const float* __restrict__ b_rattn, const float* __restrict__ memory,
    const float* __restrict__ W_ih, const float* __restrict__ b_ih,
    const float* __restrict__ b_hh, const float* __restrict__ W_out,
    const float* __restrict__ b_out)
{
    __shared__ float wr[1024];
    __shared__ float red[32];
    __shared__ float bc;
    __shared__ float part[8 * 32];
    __shared__ float rd_s[32];
    const int t = threadIdx.x;
    const int lane = t & 31, w = t >> 5;

    float mx = -1e30f;
    for (int i = t; i < 1024; i += 256) { float v = b_rattn[i]; wr[i] = v; mx = fmaxf(mx, v); }
#pragma unroll
    for (int o = 16; o; o >>= 1) mx = fmaxf(mx, __shfl_xor_sync(FULLMASK, mx, o));
    if (lane == 0) red[w] = mx;
    __syncthreads();
    if (t == 0) { float m = red[0]; for (int i = 1; i < 8; i++) m = fmaxf(m, red[i]); bc = m; }
    __syncthreads();
    mx = bc;
    float s = 0.f;
    for (int i = t; i < 1024; i += 256) { float e = __expf(wr[i] - mx); wr[i] = e; s += e; }
#pragma unroll
    for (int o = 16; o; o >>= 1) s += __shfl_xor_sync(FULLMASK, s, o);
    __syncthreads();
    if (lane == 0) red[w] = s;
    __syncthreads();
    if (t == 0) { float ss = 0.f; for (int i = 0; i < 8; i++) ss += red[i]; bc = ss; }
    __syncthreads();
    const float inv = 1.f / bc;
    for (int i = t; i < 1024; i += 256) wr[i] *= inv;
    __syncthreads();

    {
        const int d = lane, pp = w;
        float acc = 0.f;
        const int m0 = pp * 128;
        for (int m = m0; m < m0 + 128; m++) acc += wr[m] * memory[m * 32 + d];
        part[pp * 32 + d] = acc;
    }
    __syncthreads();
    if (t < 32) { float r = 0.f; for (int p = 0; p < 8; p++) r += part[p * 32 + t]; rd_s[t] = r; }
    __syncthreads();

    for (int j = t; j < 1024; j += 256) {
        float g = b_ih[j] + b_hh[j];
        const float* wp = W_ih + (size_t)j * 288 + 256;
#pragma unroll
        for (int d = 0; d < 32; d++) g += wp[d] * rd_s[d];
        g_gate_bias[j] = g;
    }
    {
        float g = b_out[t];
        const float* wp = W_out + (size_t)t * 288 + 256;
#pragma unroll
        for (int d = 0; d < 32; d++) g += wp[d] * rd_s[d];
        g_out_bias[t] = g;
    }
}

// ---------------- split helpers ----------------------------------------------
__device__ __forceinline__ void split_write_A(__nv_bfloat16* dst, float v)
{
    __nv_bfloat16 hi = __float2bfloat16_rn(v);
    float r = v - __bfloat162float(hi);
    dst[0] = hi; dst[256] = __float2bfloat16_rn(r); dst[512] = hi;
}
__device__ __forceinline__ void split_write_B(__nv_bfloat16* dst, float v)
{
    __nv_bfloat16 hi = __float2bfloat16_rn(v);
    float r = v - __bfloat162float(hi);
    dst[0] = hi; dst[256] = hi; dst[512] = __float2bfloat16_rn(r);
}

// ---------------- k1: convert x + all weights (one launch) -------------------
__global__ __launch_bounds__(256) void conv_all_kernel(
    const float* __restrict__ x, const float* __restrict__ W_ih,
    const float* __restrict__ W_wattn, const float* __restrict__ W_er,
    const float* __restrict__ W_ad, const float* __restrict__ W_out)
{
    const int blk = blockIdx.x, k = threadIdx.x;
    if (blk < 2048) {
        split_write_A(g_xs + (size_t)blk * 768 + k, x[blk * 256 + k]);
    } else if (blk < 2816) {
        const int r = blk - 2048;                       // gate rows i|g|o
        const int orig = r + (r >= 256 ? 256 : 0);
        split_write_B(g_Bih + (size_t)r * 768 + k, W_ih[(size_t)orig * 288 + k]);
    } else if (blk < 3840) {
        const int rw = blk - 2816;                      // W_wattn rows
        split_write_B(g_Bcomb + (size_t)rw * 768 + k, W_wattn[(size_t)rw * 256 + k]);
    } else {
        const int rh = blk - 3840;                      // head rows
        float v;
        if (rh < 32)       v = W_er[(size_t)rh * 256 + k];
        else if (rh < 64)  v = W_ad[(size_t)(rh - 32) * 256 + k];
        else if (rh < 320) v = W_out[(size_t)(rh - 64) * 288 + k];
        else               v = 0.f;
        split_write_B(g_Bcomb + (size_t)(1024 + rh) * 768 + k, v);
    }
}

// ---------------- bf16 MMA GEMM: 64(M) x 128(N), K'=768, 3-stage cp.async ----
// MODE 0: A=g_xs, B=g_Bih (N=768),   out g_gates + gate_bias(remap)
// MODE 1: A=g_hs, B=g_Bcomb(N=1408), n<1024 -> g_ww + b_wattn; else head scatter
template <int MODE>
__global__ __launch_bounds__(256, 2) void mma_gemm(
    const __nv_bfloat16* __restrict__ A, const __nv_bfloat16* __restrict__ B,
    const float* __restrict__ bias, const float* __restrict__ b_er,
    const float* __restrict__ b_ad, float* __restrict__ out_main)
{
    __shared__ __nv_bfloat16 As[3][64][40];
    __shared__ __nv_bfloat16 Bs[3][128][40];

    const int tid = threadIdx.x;
    const int wid = tid >> 5, lane = tid & 31;
    const int m0 = blockIdx.y * 64, n0 = blockIdx.x * 128;
    const int warp_m = wid & 1, warp_n = wid >> 1;     // 2 x 4 warps, tile 32x32

    const uint32_t abase = (uint32_t)__cvta_generic_to_shared(&As[0][0][0]);
    const uint32_t bbase = (uint32_t)__cvta_generic_to_shared(&Bs[0][0][0]);

    // loader mapping: thread -> (row = tid>>2, seg = tid&3) 16B segments
    const int lrow = tid >> 2, lseg = tid & 3;
    const __nv_bfloat16* Ag = A + (size_t)(m0 + lrow) * 768 + lseg * 8;
    const __nv_bfloat16* Bg0 = B + (size_t)(n0 + lrow) * 768 + lseg * 8;
    const __nv_bfloat16* Bg1 = Bg0 + (size_t)64 * 768;
    const uint32_t adst = abase + lrow * 80 + lseg * 16;
    const uint32_t bdst0 = bbase + lrow * 80 + lseg * 16;
    const uint32_t bdst1 = bdst0 + 64 * 80;

    float acc[2][4][4];
#pragma unroll
    for (int i = 0; i < 2; i++)
#pragma unroll
        for (int j = 0; j < 4; j++)
#pragma unroll
            for (int q = 0; q < 4; q++) acc[i][j][q] = 0.f;

    const int NC = 24;   // 768/32
#pragma unroll
    for (int st = 0; st < 2; st++) {
        const int koff = st * 32;
        cpasync16(adst + st * 5120, Ag + koff);
        cpasync16(bdst0 + st * 10240, Bg0 + koff);
        cpasync16(bdst1 + st * 10240, Bg1 + koff);
        cpcommit();
    }

#pragma unroll 1
    for (int c = 0; c < NC; c++) {
        cpwait1();
        __syncthreads();
        const int buf = c % 3;
        const uint32_t ab = abase + buf * 5120;
        const uint32_t bb = bbase + buf * 10240;
#pragma unroll
        for (int kk = 0; kk < 2; kk++) {
            const int k16 = kk * 16;
            uint32_t af[2][4];
#pragma unroll
            for (int mi = 0; mi < 2; mi++) {
                const int rr = warp_m * 32 + mi * 16 + (lane & 15);
                const int cc = k16 + ((lane >> 4) << 3);
                ldsm4(af[mi][0], af[mi][1], af[mi][2], af[mi][3],
                      ab + (uint32_t)(rr * 40 + cc) * 2);
            }
            uint32_t bf[2][4];
#pragma unroll
            for (int bi = 0; bi < 2; bi++) {
                const int rr = warp_n * 32 + bi * 16 + ((lane >> 4) << 3) + (lane & 7);
                const int cc = k16 + (((lane >> 3) & 1) << 3);
                ldsm4(bf[bi][0], bf[bi][1], bf[bi][2], bf[bi][3],
                      bb + (uint32_t)(rr * 40 + cc) * 2);
            }
#pragma unroll
            for (int mi = 0; mi < 2; mi++)
#pragma unroll
                for (int nj = 0; nj < 4; nj++) {
                    const uint32_t b0 = bf[nj >> 1][(nj & 1) * 2];
                    const uint32_t b1 = bf[nj >> 1][(nj & 1) * 2 + 1];
                    mma16816(acc[mi][nj][0], acc[mi][nj][1], acc[mi][nj][2], acc[mi][nj][3],
                             af[mi][0], af[mi][1], af[mi][2], af[mi][3], b0, b1);
                }
        }
        if (c + 2 < NC) {
            const int ns = (c + 2) % 3;
            const int koff = (c + 2) * 32;
            cpasync16(adst + ns * 5120, Ag + koff);
            cpasync16(bdst0 + ns * 10240, Bg0 + koff);
            cpasync16(bdst1 + ns * 10240, Bg1 + koff);
        }
        cpcommit();
    }

    // ----- epilogue -----
    const int erow = lane >> 2;
    const int ecol = (lane & 3) * 2;
#pragma unroll
    for (int mi = 0; mi < 2; mi++) {
        const int r0 = m0 + warp_m * 32 + mi * 16 + erow;
#pragma unroll
        for (int nj = 0; nj < 4; nj++) {
            const int cbase = n0 + warp_n * 32 + nj * 8 + ecol;
            const float v0 = acc[mi][nj][0], v1 = acc[mi][nj][1];
            const float v2 = acc[mi][nj][2], v3 = acc[mi][nj][3];
            if (MODE == 0) {
                const float bz0 = g_gate_bias[cbase + (cbase >= 256 ? 256 : 0)];
                const float bz1 = g_gate_bias[cbase + 1 + (cbase + 1 >= 256 ? 256 : 0)];
                float* p0 = g_gates + (size_t)r0 * 768 + cbase;
                p0[0] = v0 + bz0; p0[1] = v1 + bz1;
                float* p1 = p0 + 8 * 768;
                p1[0] = v2 + bz0; p1[1] = v3 + bz1;
            } else {
                if (cbase < 1024) {
                    const float bz0 = bias[cbase], bz1 = bias[cbase + 1];
                    float* p0 = g_ww + (size_t)r0 * 1024 + cbase;
                    p0[0] = v0 + bz0; p0[1] = v1 + bz1;
                    float* p1 = p0 + 8 * 1024;
                    p1[0] = v2 + bz0; p1[1] = v3 + bz1;
                } else {
#pragma unroll
                    for (int q = 0; q < 4; q++) {
                        const int m = r0 + (q >= 2 ? 8 : 0);
                        const int n = cbase + (q & 1) - 1024;
                        const float vv = (q == 0) ? v0 : (q == 1) ? v1 : (q == 2) ? v2 : v3;
                        if (n < 32)        g_erase[m * 32 + n] = sigmf(vv + b_er[n]);
                        else if (n < 64)   g_add[m * 32 + n - 32] = tanhf(vv + b_ad[n - 32]);
                        else if (n < 320)  out_main[(size_t)m * 256 + n - 64] = vv + g_out_bias[n - 64];
                    }
                }
            }
        }
    }
}

// ---------------- k3: LSTM activations -> h_new split -> g_hs ----------------
__global__ __launch_bounds__(256) void activ_kernel()
{
    const int idx = blockIdx.x * 256 + threadIdx.x;
    const int b = idx >> 8, cc = idx & 255;
    const float* g = g_gates + (size_t)b * 768;
    const float ig = g[cc], gg = g[256 + cc], og = g[512 + cc];
    const float cnew = sigmf(ig) * tanhf(gg);
    split_write_A(g_hs + (size_t)b * 768 + cc, sigmf(og) * tanhf(cnew));
}

// ---------------- k5: row softmax over g_ww [2048 x 1024], in place ----------
__global__ __launch_bounds__(256) void softmax1024()
{
    __shared__ float red[8];
    __shared__ float bc;
    float* p = g_ww + (size_t)blockIdx.x * 1024;
    const int t = threadIdx.x, lane = t & 31, w = t >> 5;
    float v[4];
    float mx = -1e30f;
#pragma unroll
    for (int i = 0; i < 4; i++) { v[i] = p[t + i * 256]; mx = fmaxf(mx, v[i]); }
#pragma unroll
    for (int o = 16; o; o >>= 1) mx = fmaxf(mx, __shfl_xor_sync(FULLMASK, mx, o));
    if (lane == 0) red[w] = mx;
    __syncthreads();
    if (t == 0) { float m = red[0]; for (int i = 1; i < 8; i++) m = fmaxf(m, red[i]); bc = m; }
    __syncthreads();
    mx = bc;
    float s = 0.f;
#pragma unroll
    for (int i = 0; i < 4; i++) { v[i] = __expf(v[i] - mx); s += v[i]; }
#pragma unroll
    for (int o = 16; o; o >>= 1) s += __shfl_xor_sync(FULLMASK, s, o);
    __syncthreads();
    if (lane == 0) red[w] = s;
    __syncthreads();
    if (t == 0) { float ss = 0.f; for (int i = 0; i < 8; i++) ss += red[i]; bc = ss; }
    __syncthreads();
    const float inv = 1.f / bc;
#pragma unroll
    for (int i = 0; i < 4; i++) p[t + i * 256] = v[i] * inv;
}

// ---------------- k6: write_data, memory-slice reuse (268 MB stores) ---------
// block = (64 m-rows, 64 batches); memory slice cached in smem; grid (16, 32).
__global__ __launch_bounds__(256) void write_mem2(
    const float* __restrict__ memory, float* __restrict__ outw)
{
    __shared__ float msl[64 * 32];
    const int m0 = blockIdx.x * 64;
    const int b0 = blockIdx.y * 64;
    const int t = threadIdx.x;

    {
        const float4* src = (const float4*)(memory + m0 * 32);
        float4* dst = (float4*)msl;
        dst[t] = src[t];
        dst[t + 256] = src[t + 256];
    }
    __syncthreads();

    const int row = t >> 3;              // 0..31 (second task: +32)
    const int d4 = (t & 7) * 4;
    const float4 mv0 = *(const float4*)&msl[row * 32 + d4];
    const float4 mv1 = *(const float4*)&msl[(row + 32) * 32 + d4];

#pragma unroll 2
    for (int bi = 0; bi < 64; bi++) {
        const int b = b0 + bi;
        const float4 ev = *(const float4*)(g_erase + b * 32 + d4);
        const float4 av = *(const float4*)(g_add + b * 32 + d4);
        const float* wwb = g_ww + (size_t)b * 1024 + m0;
        const float w0 = wwb[row], w1 = wwb[row + 32];
        float* ob = outw + (size_t)b * 32768 + (size_t)m0 * 32;
        float4 r;
        r.x = mv0.x - w0 * (mv0.x * ev.x - av.x);
        r.y = mv0.y - w0 * (mv0.y * ev.y - av.y);
        r.z = mv0.z - w0 * (mv0.z * ev.z - av.z);
        r.w = mv0.w - w0 * (mv0.w * ev.w - av.w);
        __stcs((float4*)(ob + row * 32 + d4), r);
        r.x = mv1.x - w1 * (mv1.x * ev.x - av.x);
        r.y = mv1.y - w1 * (mv1.y * ev.y - av.y);
        r.z = mv1.z - w1 * (mv1.z * ev.z - av.z);
        r.w = mv1.w - w1 * (mv1.w * ev.w - av.w);
        __stcs((float4*)(ob + (row + 32) * 32 + d4), r);
    }
}

// ---------------- launch -----------------------------------------------------
extern "C" void kernel_launch(void* const* d_in, const int* in_sizes, int n_in,
                              void* d_out, int out_size)
{
    const float* x       = (const float*)d_in[0];
    const float* memory  = (const float*)d_in[1];
    const float* b_rattn = (const float*)d_in[3];
    const float* W_ih    = (const float*)d_in[4];
    const float* b_ih    = (const float*)d_in[6];
    const float* b_hh    = (const float*)d_in[7];
    const float* W_wattn = (const float*)d_in[8];
    const float* b_wattn = (const float*)d_in[9];
    const float* W_er    = (const float*)d_in[10];
    const float* b_er    = (const float*)d_in[11];
    const float* W_ad    = (const float*)d_in[12];
    const float* b_ad    = (const float*)d_in[13];
    const float* W_out   = (const float*)d_in[14];
    const float* b_out   = (const float*)d_in[15];
    float* out = (float*)d_out;

    __nv_bfloat16 *xs, *hs, *Bih, *Bcomb;
    cudaGetSymbolAddress((void**)&xs, g_xs);
    cudaGetSymbolAddress((void**)&hs, g_hs);
    cudaGetSymbolAddress((void**)&Bih, g_Bih);
    cudaGetSymbolAddress((void**)&Bcomb, g_Bcomb);

    conv_all_kernel<<<4224, 256>>>(x, W_ih, W_wattn, W_er, W_ad, W_out);
    setup_kernel<<<1, 256>>>(b_rattn, memory, W_ih, b_ih, b_hh, W_out, b_out);
    mma_gemm<0><<<dim3(6, 32), 256>>>(xs, Bih, nullptr, nullptr, nullptr, nullptr);
    activ_kernel<<<2048, 256>>>();
    mma_gemm<1><<<dim3(11, 32), 256>>>(hs, Bcomb, b_wattn, b_er, b_ad, out);
    softmax1024<<<2048, 256>>>();
    write_mem2<<<dim3(16, 32), 256>>>(memory, out + 2048 * 256);
}

// round 8
// speedup vs baseline: 1.8020x; 1.0027x over previous
#include <cuda_runtime.h>
#include <cuda_bf16.h>
#include <cstdint>

#define FULLMASK 0xffffffffu

// ---------------- scratch (device globals; no allocations) -------------------
__device__ float g_gates[2048 * 768];          // pre-activation gates (i|g|o)
__device__ float g_ww[2048 * 1024];            // write-attn logits -> weights
__device__ float g_erase[2048 * 32];
__device__ float g_add[2048 * 32];
__device__ float g_gate_bias[1024];            // indexed by ORIGINAL 1024 gate idx
__device__ float g_out_bias[256];

// bf16 split buffers (K expanded 256 -> 768: A=[hi|lo|hi], B=[hi|hi|lo])
__device__ __nv_bfloat16 g_xs[2048 * 768];
__device__ __nv_bfloat16 g_hs[2048 * 768];
__device__ __nv_bfloat16 g_Bih[768 * 768];     // W_ih gate rows (i|g|o)
__device__ __nv_bfloat16 g_Bcomb[1408 * 768];  // [W_wattn(1024) | W_er|W_ad|W_out|pad]

__device__ __forceinline__ float sigmf(float x) { return 1.f / (1.f + __expf(-x)); }

// ---------------- PTX helpers -------------------------------------------------
__device__ __forceinline__ void ldsm4(uint32_t& r0, uint32_t& r1, uint32_t& r2,
                                      uint32_t& r3, uint32_t addr)
{
    asm volatile("ldmatrix.sync.aligned.m8n8.x4.shared.b16 {%0,%1,%2,%3}, [%4];"
                 : "=r"(r0), "=r"(r1), "=r"(r2), "=r"(r3) : "r"(addr));
}
__device__ __forceinline__ void mma16816(float& d0, float& d1, float& d2, float& d3,
                                         uint32_t a0, uint32_t a1, uint32_t a2, uint32_t a3,
                                         uint32_t b0, uint32_t b1)
{
    asm volatile(
        "mma.sync.aligned.m16n8k16.row.col.f32.bf16.bf16.f32 "
        "{%0,%1,%2,%3}, {%4,%5,%6,%7}, {%8,%9}, {%0,%1,%2,%3};"
        : "+f"(d0), "+f"(d1), "+f"(d2), "+f"(d3)
        : "r"(a0), "r"(a1), "r"(a2), "r"(a3), "r"(b0), "r"(b1));
}
__device__ __forceinline__ void cpasync16(uint32_t dst, const void* src)
{
    asm volatile("cp.async.cg.shared.global [%0], [%1], 16;" :: "r"(dst), "l"(src));
}
__device__ __forceinline__ void cpcommit() { asm volatile("cp.async.commit_group;"); }
__device__ __forceinline__ void cpwait1() { asm volatile("cp.async.wait_group 1;"); }

__device__ __forceinline__ uint32_t packbf2(float a, float b)
{
    __nv_bfloat162 t = __floats2bfloat162_rn(a, b);
    return *reinterpret_cast<uint32_t*>(&t);
}

// ---------------- k0: setup — softmax(b_rattn), rd, folded biases -------------
__global__ __launch_bounds__(256) void setup_kernel(
    const float* __restrict__ b_rattn, const float* __restrict__ memory,
    const float* __restrict__ W_ih, const float* __restrict__ b_ih,
    const float* __restrict__ b_hh, const float* __restrict__ W_out,
    const float* __restrict__ b_out)
{
    __shared__ float wr[1024];
    __shared__ float red[32];
    __shared__ float bc;
    __shared__ float part[8 * 32];
    __shared__ float rd_s[32];
    const int t = threadIdx.x;
    const int lane = t & 31, w = t >> 5;

    float mx = -1e30f;
    for (int i = t; i < 1024; i += 256) { float v = b_rattn[i]; wr[i] = v; mx = fmaxf(mx, v); }
#pragma unroll
    for (int o = 16; o; o >>= 1) mx = fmaxf(mx, __shfl_xor_sync(FULLMASK, mx, o));
    if (lane == 0) red[w] = mx;
    __syncthreads();
    if (t == 0) { float m = red[0]; for (int i = 1; i < 8; i++) m = fmaxf(m, red[i]); bc = m; }
    __syncthreads();
    mx = bc;
    float s = 0.f;
    for (int i = t; i < 1024; i += 256) { float e = __expf(wr[i] - mx); wr[i] = e; s += e; }
#pragma unroll
    for (int o = 16; o; o >>= 1) s += __shfl_xor_sync(FULLMASK, s, o);
    __syncthreads();
    if (lane == 0) red[w] = s;
    __syncthreads();
    if (t == 0) { float ss = 0.f; for (int i = 0; i < 8; i++) ss += red[i]; bc = ss; }
    __syncthreads();
    const float inv = 1.f / bc;
    for (int i = t; i < 1024; i += 256) wr[i] *= inv;
    __syncthreads();

    {
        const int d = lane, pp = w;
        float acc = 0.f;
        const int m0 = pp * 128;
        for (int m = m0; m < m0 + 128; m++) acc += wr[m] * memory[m * 32 + d];
        part[pp * 32 + d] = acc;
    }
    __syncthreads();
    if (t < 32) { float r = 0.f; for (int p = 0; p < 8; p++) r += part[p * 32 + t]; rd_s[t] = r; }
    __syncthreads();

    for (int j = t; j < 1024; j += 256) {
        float g = b_ih[j] + b_hh[j];
        const float* wp = W_ih + (size_t)j * 288 + 256;
#pragma unroll
        for (int d = 0; d < 32; d++) g += wp[d] * rd_s[d];
        g_gate_bias[j] = g;
    }
    {
        float g = b_out[t];
        const float* wp = W_out + (size_t)t * 288 + 256;
#pragma unroll
        for (int d = 0; d < 32; d++) g += wp[d] * rd_s[d];
        g_out_bias[t] = g;
    }
}

// ---------------- vectorized split writers ------------------------------------
__device__ __forceinline__ void splitA4(__nv_bfloat16* dst, float4 v)
{
    const float h0 = __bfloat162float(__float2bfloat16_rn(v.x));
    const float h1 = __bfloat162float(__float2bfloat16_rn(v.y));
    const float h2 = __bfloat162float(__float2bfloat16_rn(v.z));
    const float h3 = __bfloat162float(__float2bfloat16_rn(v.w));
    const uint2 hi = make_uint2(packbf2(v.x, v.y), packbf2(v.z, v.w));
    const uint2 lo = make_uint2(packbf2(v.x - h0, v.y - h1), packbf2(v.z - h2, v.w - h3));
    *(uint2*)(dst) = hi;
    *(uint2*)(dst + 256) = lo;
    *(uint2*)(dst + 512) = hi;
}
__device__ __forceinline__ void splitB4(__nv_bfloat16* dst, float4 v)
{
    const float h0 = __bfloat162float(__float2bfloat16_rn(v.x));
    const float h1 = __bfloat162float(__float2bfloat16_rn(v.y));
    const float h2 = __bfloat162float(__float2bfloat16_rn(v.z));
    const float h3 = __bfloat162float(__float2bfloat16_rn(v.w));
    const uint2 hi = make_uint2(packbf2(v.x, v.y), packbf2(v.z, v.w));
    const uint2 lo = make_uint2(packbf2(v.x - h0, v.y - h1), packbf2(v.z - h2, v.w - h3));
    *(uint2*)(dst) = hi;
    *(uint2*)(dst + 256) = hi;
    *(uint2*)(dst + 512) = lo;
}

// ---------------- k1: convert x + all weights (one launch, x4 vectorized) ----
__global__ __launch_bounds__(256) void conv_all_kernel(
    const float* __restrict__ x, const float* __restrict__ W_ih,
    const float* __restrict__ W_wattn, const float* __restrict__ W_er,
    const float* __restrict__ W_ad, const float* __restrict__ W_out)
{
    const int vr = blockIdx.x * 4 + (threadIdx.x >> 6);
    const int k = (threadIdx.x & 63) * 4;
    if (vr < 2048) {
        splitA4(g_xs + (size_t)vr * 768 + k, *(const float4*)(x + (size_t)vr * 256 + k));
    } else if (vr < 2816) {
        const int r = vr - 2048;
        const int orig = r + (r >= 256 ? 256 : 0);
        splitB4(g_Bih + (size_t)r * 768 + k, *(const float4*)(W_ih + (size_t)orig * 288 + k));
    } else if (vr < 3840) {
        const int rw = vr - 2816;
        splitB4(g_Bcomb + (size_t)rw * 768 + k, *(const float4*)(W_wattn + (size_t)rw * 256 + k));
    } else {
        const int rh = vr - 3840;
        float4 v = make_float4(0.f, 0.f, 0.f, 0.f);
        if (rh < 32)       v = *(const float4*)(W_er + (size_t)rh * 256 + k);
        else if (rh < 64)  v = *(const float4*)(W_ad + (size_t)(rh - 32) * 256 + k);
        else if (rh < 320) v = *(const float4*)(W_out + (size_t)(rh - 64) * 288 + k);
        splitB4(g_Bcomb + (size_t)(1024 + rh) * 768 + k, v);
    }
}

// ---------------- bf16 MMA GEMM: 64(M) x 128(N), K'=768, 3-stage cp.async ----
// (exact R5-passing configuration: static smem, wait_group 1, unconditional commit)
// MODE 0: A=g_xs, B=g_Bih (N=768),   out g_gates + gate_bias(remap)
// MODE 1: A=g_hs, B=g_Bcomb(N=1408), n<1024 -> g_ww + b_wattn; else head scatter
template <int MODE>
__global__ __launch_bounds__(256, 2) void mma_gemm(
    const __nv_bfloat16* __restrict__ A, const __nv_bfloat16* __restrict__ B,
    const float* __restrict__ bias, const float* __restrict__ b_er,
    const float* __restrict__ b_ad, float* __restrict__ out_main)
{
    __shared__ __nv_bfloat16 As[3][64][40];
    __shared__ __nv_bfloat16 Bs[3][128][40];

    const int tid = threadIdx.x;
    const int wid = tid >> 5, lane = tid & 31;
    const int m0 = blockIdx.y * 64, n0 = blockIdx.x * 128;
    const int warp_m = wid & 1, warp_n = wid >> 1;     // 2 x 4 warps, tile 32x32

    const uint32_t abase = (uint32_t)__cvta_generic_to_shared(&As[0][0][0]);
    const uint32_t bbase = (uint32_t)__cvta_generic_to_shared(&Bs[0][0][0]);

    const int lrow = tid >> 2, lseg = tid & 3;
    const __nv_bfloat16* Ag = A + (size_t)(m0 + lrow) * 768 + lseg * 8;
    const __nv_bfloat16* Bg0 = B + (size_t)(n0 + lrow) * 768 + lseg * 8;
    const __nv_bfloat16* Bg1 = Bg0 + (size_t)64 * 768;
    const uint32_t adst = abase + lrow * 80 + lseg * 16;
    const uint32_t bdst0 = bbase + lrow * 80 + lseg * 16;
    const uint32_t bdst1 = bdst0 + 64 * 80;

    float acc[2][4][4];
#pragma unroll
    for (int i = 0; i < 2; i++)
#pragma unroll
        for (int j = 0; j < 4; j++)
#pragma unroll
            for (int q = 0; q < 4; q++) acc[i][j][q] = 0.f;

    const int NC = 24;   // 768/32
#pragma unroll
    for (int st = 0; st < 2; st++) {
        const int koff = st * 32;
        cpasync16(adst + st * 5120, Ag + koff);
        cpasync16(bdst0 + st * 10240, Bg0 + koff);
        cpasync16(bdst1 + st * 10240, Bg1 + koff);
        cpcommit();
    }

#pragma unroll 1
    for (int c = 0; c < NC; c++) {
        cpwait1();
        __syncthreads();
        const int buf = c % 3;
        const uint32_t ab = abase + buf * 5120;
        const uint32_t bb = bbase + buf * 10240;
#pragma unroll
        for (int kk = 0; kk < 2; kk++) {
            const int k16 = kk * 16;
            uint32_t af[2][4];
#pragma unroll
            for (int mi = 0; mi < 2; mi++) {
                const int rr = warp_m * 32 + mi * 16 + (lane & 15);
                const int cc = k16 + ((lane >> 4) << 3);
                ldsm4(af[mi][0], af[mi][1], af[mi][2], af[mi][3],
                      ab + (uint32_t)(rr * 40 + cc) * 2);
            }
            uint32_t bf[2][4];
#pragma unroll
            for (int bi = 0; bi < 2; bi++) {
                const int rr = warp_n * 32 + bi * 16 + ((lane >> 4) << 3) + (lane & 7);
                const int cc = k16 + (((lane >> 3) & 1) << 3);
                ldsm4(bf[bi][0], bf[bi][1], bf[bi][2], bf[bi][3],
                      bb + (uint32_t)(rr * 40 + cc) * 2);
            }
#pragma unroll
            for (int mi = 0; mi < 2; mi++)
#pragma unroll
                for (int nj = 0; nj < 4; nj++) {
                    const uint32_t b0 = bf[nj >> 1][(nj & 1) * 2];
                    const uint32_t b1 = bf[nj >> 1][(nj & 1) * 2 + 1];
                    mma16816(acc[mi][nj][0], acc[mi][nj][1], acc[mi][nj][2], acc[mi][nj][3],
                             af[mi][0], af[mi][1], af[mi][2], af[mi][3], b0, b1);
                }
        }
        if (c + 2 < NC) {
            const int ns = (c + 2) % 3;
            const int koff = (c + 2) * 32;
            cpasync16(adst + ns * 5120, Ag + koff);
            cpasync16(bdst0 + ns * 10240, Bg0 + koff);
            cpasync16(bdst1 + ns * 10240, Bg1 + koff);
        }
        cpcommit();
    }

    // ----- epilogue -----
    const int erow = lane >> 2;
    const int ecol = (lane & 3) * 2;
#pragma unroll
    for (int mi = 0; mi < 2; mi++) {
        const int r0 = m0 + warp_m * 32 + mi * 16 + erow;
#pragma unroll
        for (int nj = 0; nj < 4; nj++) {
            const int cbase = n0 + warp_n * 32 + nj * 8 + ecol;
            const float v0 = acc[mi][nj][0], v1 = acc[mi][nj][1];
            const float v2 = acc[mi][nj][2], v3 = acc[mi][nj][3];
            if (MODE == 0) {
                const float bz0 = g_gate_bias[cbase + (cbase >= 256 ? 256 : 0)];
                const float bz1 = g_gate_bias[cbase + 1 + (cbase + 1 >= 256 ? 256 : 0)];
                float* p0 = g_gates + (size_t)r0 * 768 + cbase;
                p0[0] = v0 + bz0; p0[1] = v1 + bz1;
                float* p1 = p0 + 8 * 768;
                p1[0] = v2 + bz0; p1[1] = v3 + bz1;
            } else {
                if (cbase < 1024) {
                    const float bz0 = bias[cbase], bz1 = bias[cbase + 1];
                    float* p0 = g_ww + (size_t)r0 * 1024 + cbase;
                    p0[0] = v0 + bz0; p0[1] = v1 + bz1;
                    float* p1 = p0 + 8 * 1024;
                    p1[0] = v2 + bz0; p1[1] = v3 + bz1;
                } else {
#pragma unroll
                    for (int q = 0; q < 4; q++) {
                        const int m = r0 + (q >= 2 ? 8 : 0);
                        const int n = cbase + (q & 1) - 1024;
                        const float vv = (q == 0) ? v0 : (q == 1) ? v1 : (q == 2) ? v2 : v3;
                        if (n < 32)        g_erase[m * 32 + n] = sigmf(vv + b_er[n]);
                        else if (n < 64)   g_add[m * 32 + n - 32] = tanhf(vv + b_ad[n - 32]);
                        else if (n < 320)  out_main[(size_t)m * 256 + n - 64] = vv + g_out_bias[n - 64];
                    }
                }
            }
        }
    }
}

// ---------------- k3: LSTM activations (x4 vectorized) -> g_hs ---------------
__global__ __launch_bounds__(256) void activ_kernel()
{
    const int idx4 = (blockIdx.x * 256 + threadIdx.x) * 4;   // 2048*256 elems
    const int b = idx4 >> 8, cc = idx4 & 255;
    const float* g = g_gates + (size_t)b * 768 + cc;
    const float4 ig = *(const float4*)(g);
    const float4 gg = *(const float4*)(g + 256);
    const float4 og = *(const float4*)(g + 512);
    float h[4];
    h[0] = sigmf(og.x) * tanhf(sigmf(ig.x) * tanhf(gg.x));
    h[1] = sigmf(og.y) * tanhf(sigmf(ig.y) * tanhf(gg.y));
    h[2] = sigmf(og.z) * tanhf(sigmf(ig.z) * tanhf(gg.z));
    h[3] = sigmf(og.w) * tanhf(sigmf(ig.w) * tanhf(gg.w));
    splitA4(g_hs + (size_t)b * 768 + cc, make_float4(h[0], h[1], h[2], h[3]));
}

// ---------------- k5: row softmax over g_ww [2048 x 1024], float4 ------------
__global__ __launch_bounds__(256) void softmax1024()
{
    __shared__ float red[8];
    __shared__ float bc;
    float4* p = (float4*)(g_ww + (size_t)blockIdx.x * 1024);
    const int t = threadIdx.x, lane = t & 31, w = t >> 5;
    float4 v = p[t];
    float mx = fmaxf(fmaxf(v.x, v.y), fmaxf(v.z, v.w));
#pragma unroll
    for (int o = 16; o; o >>= 1) mx = fmaxf(mx, __shfl_xor_sync(FULLMASK, mx, o));
    if (lane == 0) red[w] = mx;
    __syncthreads();
    if (t == 0) { float m = red[0]; for (int i = 1; i < 8; i++) m = fmaxf(m, red[i]); bc = m; }
    __syncthreads();
    mx = bc;
    v.x = __expf(v.x - mx); v.y = __expf(v.y - mx);
    v.z = __expf(v.z - mx); v.w = __expf(v.w - mx);
    float s = v.x + v.y + v.z + v.w;
#pragma unroll
    for (int o = 16; o; o >>= 1) s += __shfl_xor_sync(FULLMASK, s, o);
    __syncthreads();
    if (lane == 0) red[w] = s;
    __syncthreads();
    if (t == 0) { float ss = 0.f; for (int i = 0; i < 8; i++) ss += red[i]; bc = ss; }
    __syncthreads();
    const float inv = 1.f / bc;
    v.x *= inv; v.y *= inv; v.z *= inv; v.w *= inv;
    p[t] = v;
}

// ---------------- k6: write_data, memory-slice reuse (268 MB stores) ---------
__global__ __launch_bounds__(256) void write_mem2(
    const float* __restrict__ memory, float* __restrict__ outw)
{
    __shared__ float msl[64 * 32];
    const int m0 = blockIdx.x * 64;
    const int b0 = blockIdx.y * 64;
    const int t = threadIdx.x;

    {
        const float4* src = (const float4*)(memory + m0 * 32);
        float4* dst = (float4*)msl;
        dst[t] = src[t];
        dst[t + 256] = src[t + 256];
    }
    __syncthreads();

    const int row = t >> 3;
    const int d4 = (t & 7) * 4;
    const float4 mv0 = *(const float4*)&msl[row * 32 + d4];
    const float4 mv1 = *(const float4*)&msl[(row + 32) * 32 + d4];

#pragma unroll 4
    for (int bi = 0; bi < 64; bi++) {
        const int b = b0 + bi;
        const float4 ev = *(const float4*)(g_erase + b * 32 + d4);
        const float4 av = *(const float4*)(g_add + b * 32 + d4);
        const float* wwb = g_ww + (size_t)b * 1024 + m0;
        const float w0 = wwb[row], w1 = wwb[row + 32];
        float* ob = outw + (size_t)b * 32768 + (size_t)m0 * 32;
        float4 r;
        r.x = mv0.x - w0 * (mv0.x * ev.x - av.x);
        r.y = mv0.y - w0 * (mv0.y * ev.y - av.y);
        r.z = mv0.z - w0 * (mv0.z * ev.z - av.z);
        r.w = mv0.w - w0 * (mv0.w * ev.w - av.w);
        __stcs((float4*)(ob + row * 32 + d4), r);
        r.x = mv1.x - w1 * (mv1.x * ev.x - av.x);
        r.y = mv1.y - w1 * (mv1.y * ev.y - av.y);
        r.z = mv1.z - w1 * (mv1.z * ev.z - av.z);
        r.w = mv1.w - w1 * (mv1.w * ev.w - av.w);
        __stcs((float4*)(ob + (row + 32) * 32 + d4), r);
    }
}

// ---------------- launch -----------------------------------------------------
extern "C" void kernel_launch(void* const* d_in, const int* in_sizes, int n_in,
                              void* d_out, int out_size)
{
    const float* x       = (const float*)d_in[0];
    const float* memory  = (const float*)d_in[1];
    const float* b_rattn = (const float*)d_in[3];
    const float* W_ih    = (const float*)d_in[4];
    const float* b_ih    = (const float*)d_in[6];
    const float* b_hh    = (const float*)d_in[7];
    const float* W_wattn = (const float*)d_in[8];
    const float* b_wattn = (const float*)d_in[9];
    const float* W_er    = (const float*)d_in[10];
    const float* b_er    = (const float*)d_in[11];
    const float* W_ad    = (const float*)d_in[12];
    const float* b_ad    = (const float*)d_in[13];
    const float* W_out   = (const float*)d_in[14];
    const float* b_out   = (const float*)d_in[15];
    float* out = (float*)d_out;

    __nv_bfloat16 *xs, *hs, *Bih, *Bcomb;
    cudaGetSymbolAddress((void**)&xs, g_xs);
    cudaGetSymbolAddress((void**)&hs, g_hs);
    cudaGetSymbolAddress((void**)&Bih, g_Bih);
    cudaGetSymbolAddress((void**)&Bcomb, g_Bcomb);

    conv_all_kernel<<<1056, 256>>>(x, W_ih, W_wattn, W_er, W_ad, W_out);
    setup_kernel<<<1, 256>>>(b_rattn, memory, W_ih, b_ih, b_hh, W_out, b_out);
    mma_gemm<0><<<dim3(6, 32), 256>>>(xs, Bih, nullptr, nullptr, nullptr, nullptr);
    activ_kernel<<<512, 256>>>();
    mma_gemm<1><<<dim3(11, 32), 256>>>(hs, Bcomb, b_wattn, b_er, b_ad, out);
    softmax1024<<<2048, 256>>>();
    write_mem2<<<dim3(16, 32), 256>>>(memory, out + 2048 * 256);
}